// round 14
// baseline (speedup 1.0000x reference)
#include <cuda_runtime.h>
#include <cuda_fp16.h>
#include <cstdint>

#define BB   16
#define NPTS 4096
#define MPTS 1024
#define CH   256
#define K1   512
#define BN_EPS 1e-5f

// ---------------- scratch ----------------
__device__ __align__(16) __half g_kft[(size_t)BB * MPTS * CH];
__device__ __align__(16) __half g_Hh[(size_t)BB * NPTS * CH];
__device__ __align__(16) __half g_Y2h[(size_t)BB * NPTS * CH];
__device__ __align__(16) __half g_W1h[CH * K1];
__device__ __align__(16) __half g_W2h[CH * CH];
__device__ int   g_idx3[BB * NPTS * 3];
__device__ float g_w3[BB * NPTS * 3];
__device__ float g_sum1[CH], g_sq1[CH], g_sum2[CH], g_sq2[CH];

// ---------------- helpers ----------------
__device__ __forceinline__ void cp16(uint32_t saddr, const void* g) {
    asm volatile("cp.async.ca.shared.global [%0], [%1], 16;" :: "r"(saddr), "l"(g));
}
__device__ __forceinline__ uint32_t smem_u32(const void* p) {
    uint32_t a;
    asm("{ .reg .u64 t; cvta.to.shared.u64 t, %1; cvt.u32.u64 %0, t; }" : "=r"(a) : "l"(p));
    return a;
}
__device__ __forceinline__ void ldm_x4(uint32_t* r, uint32_t addr) {
    asm volatile("ldmatrix.sync.aligned.m8n8.x4.shared.b16 {%0,%1,%2,%3}, [%4];"
                 : "=r"(r[0]), "=r"(r[1]), "=r"(r[2]), "=r"(r[3]) : "r"(addr));
}
__device__ __forceinline__ void ldm_x4t(uint32_t* r, uint32_t addr) {
    asm volatile("ldmatrix.sync.aligned.m8n8.x4.trans.shared.b16 {%0,%1,%2,%3}, [%4];"
                 : "=r"(r[0]), "=r"(r[1]), "=r"(r[2]), "=r"(r[3]) : "r"(addr));
}
__device__ __forceinline__ void mma_f16(float* d, const uint32_t* a, const uint32_t* b) {
    asm volatile(
        "mma.sync.aligned.m16n8k16.row.col.f32.f16.f16.f32 "
        "{%0,%1,%2,%3}, {%4,%5,%6,%7}, {%8,%9}, {%0,%1,%2,%3};"
        : "+f"(d[0]), "+f"(d[1]), "+f"(d[2]), "+f"(d[3])
        : "r"(a[0]), "r"(a[1]), "r"(a[2]), "r"(a[3]), "r"(b[0]), "r"(b[1]));
}

// ---------------- prep ----------------
__global__ void prep_kernel(const float* __restrict__ W1, const float* __restrict__ W2) {
    int blk = blockIdx.x;
    int t = threadIdx.x;
    if (blk < CH * K1 / 256) {
        int i = blk * 256 + t;
        g_W1h[i] = __float2half_rn(W1[i]);
    } else if (blk < CH * K1 / 256 + CH * CH / 256) {
        int i = (blk - CH * K1 / 256) * 256 + t;
        g_W2h[i] = __float2half_rn(W2[i]);
    } else {
        g_sum1[t] = 0.f; g_sq1[t] = 0.f; g_sum2[t] = 0.f; g_sq2[t] = 0.f;
    }
}

// ---------------- 3-NN + weights ----------------
__global__ void nn_kernel(const float* __restrict__ unknown, const float* __restrict__ known) {
    __shared__ float4 sk[MPTS];
    int b = blockIdx.y;
    const float* kb = known + (size_t)b * MPTS * 3;
    for (int j = threadIdx.x; j < MPTS; j += blockDim.x) {
        float kx = kb[j * 3 + 0], ky = kb[j * 3 + 1], kz = kb[j * 3 + 2];
        sk[j] = make_float4(kx, ky, kz, kx * kx + ky * ky + kz * kz);
    }
    __syncthreads();
    int i = blockIdx.x * blockDim.x + threadIdx.x;
    const float* u = unknown + ((size_t)b * NPTS + i) * 3;
    float ux = u[0], uy = u[1], uz = u[2];
    float ax = -2.f * ux, ay = -2.f * uy, az = -2.f * uz;
    float b0 = 3.4e38f, b1 = 3.4e38f, b2 = 3.4e38f;
    int i0 = 0, i1 = 0, i2 = 0;
    #pragma unroll 4
    for (int j = 0; j < MPTS; j++) {
        float4 k4 = sk[j];
        float s = fmaf(k4.x, ax, fmaf(k4.y, ay, fmaf(k4.z, az, k4.w)));
        if (s < b2) {
            if (s < b1) {
                if (s < b0) { b2 = b1; i2 = i1; b1 = b0; i1 = i0; b0 = s; i0 = j; }
                else        { b2 = b1; i2 = i1; b1 = s;  i1 = j; }
            } else          { b2 = s;  i2 = j; }
        }
    }
    float4 k0 = sk[i0], k1 = sk[i1], k2 = sk[i2];
    float d0 = (ux - k0.x) * (ux - k0.x) + (uy - k0.y) * (uy - k0.y) + (uz - k0.z) * (uz - k0.z);
    float d1 = (ux - k1.x) * (ux - k1.x) + (uy - k1.y) * (uy - k1.y) + (uz - k1.z) * (uz - k1.z);
    float d2 = (ux - k2.x) * (ux - k2.x) + (uy - k2.y) * (uy - k2.y) + (uz - k2.z) * (uz - k2.z);
    float r0 = 1.0f / (d0 + 1e-8f), r1 = 1.0f / (d1 + 1e-8f), r2 = 1.0f / (d2 + 1e-8f);
    float inv = 1.0f / (r0 + r1 + r2);
    size_t base = ((size_t)b * NPTS + i) * 3;
    g_idx3[base] = i0; g_idx3[base + 1] = i1; g_idx3[base + 2] = i2;
    g_w3[base] = r0 * inv; g_w3[base + 1] = r1 * inv; g_w3[base + 2] = r2 * inv;
}

// ---------------- known_feats transpose ----------------
__global__ void kft_kernel(const float* __restrict__ kf) {
    __shared__ float tile[32][33];
    int b = blockIdx.z, c0 = blockIdx.y * 32, j0 = blockIdx.x * 32;
    const float* src = kf + (size_t)b * CH * MPTS;
    for (int r = threadIdx.y; r < 32; r += 8)
        tile[r][threadIdx.x] = src[(size_t)(c0 + r) * MPTS + j0 + threadIdx.x];
    __syncthreads();
    __half* dst = g_kft + (size_t)b * MPTS * CH;
    for (int r = threadIdx.y; r < 32; r += 8)
        dst[(size_t)(j0 + r) * CH + c0 + threadIdx.x] = __float2half_rn(tile[threadIdx.x][r]);
}

// ---------------- GEMM geometry (2-stage, 2 blocks/SM) ----------------
#define HS      72
#define RS2H    136
#define ATILE_B (128 * HS * 2)
#define STAGE_B (2 * ATILE_B)
#define GEMM1_SMEM (2 * STAGE_B + 1024 + 4096)
#define GEMM2_SMEM (2 * STAGE_B + 2048)

// ---------------- direct-store epilogue + stats ----------------
#define GEMM_EPILOGUE(Dg)                                                              \
    do {                                                                               \
        _Pragma("unroll")                                                              \
        for (int mi = 0; mi < 4; mi++) {                                               \
            int row0 = i0 + wy * 64 + mi * 16 + g;                                     \
            _Pragma("unroll")                                                          \
            for (int ni = 0; ni < 4; ni++) {                                           \
                int col = o0 + wx * 32 + ni * 8 + 2 * c4;                              \
                *(__half2*)((Dg) + ((size_t)b * NPTS + row0) * CH + col) =             \
                    __floats2half2_rn(acc[mi][ni][0], acc[mi][ni][1]);                 \
                *(__half2*)((Dg) + ((size_t)b * NPTS + row0 + 8) * CH + col) =         \
                    __floats2half2_rn(acc[mi][ni][2], acc[mi][ni][3]);                 \
            }                                                                          \
        }                                                                              \
        _Pragma("unroll")                                                              \
        for (int ni = 0; ni < 4; ni++) {                                               \
            float s0 = 0.f, s1 = 0.f, q0 = 0.f, q1 = 0.f;                              \
            _Pragma("unroll")                                                          \
            for (int mi = 0; mi < 4; mi++) {                                           \
                const float* a = acc[mi][ni];                                          \
                s0 += a[0] + a[2]; s1 += a[1] + a[3];                                  \
                q0 += a[0] * a[0] + a[2] * a[2];                                       \
                q1 += a[1] * a[1] + a[3] * a[3];                                       \
            }                                                                          \
            int lc = wx * 32 + ni * 8 + 2 * c4;                                        \
            atomicAdd(&ssum[lc], s0); atomicAdd(&ssum[lc + 1], s1);                    \
            atomicAdd(&ssq[lc], q0);  atomicAdd(&ssq[lc + 1], q1);                     \
        }                                                                              \
        __syncthreads();                                                               \
        if (tid < 128) {                                                               \
            atomicAdd(&sums[o0 + tid], ssum[tid]);                                     \
            atomicAdd(&sqs[o0 + tid], ssq[tid]);                                       \
        }                                                                              \
    } while (0)

// ---------------- GEMM1: A = [3NN-interp(kft) | uf(f32, converted inline)], B = W1h ----------------
__global__ void __launch_bounds__(256, 2) gemm1_f(const float* __restrict__ uf,
                                                  __half* __restrict__ Dg,
                                                  float* __restrict__ sums,
                                                  float* __restrict__ sqs) {
    extern __shared__ char smc[];
    const uint32_t sbase = smem_u32(smc);
    float* ssum = (float*)(smc + 2 * STAGE_B);
    float* ssq  = ssum + 128;
    int*   sidx = (int*)(smc + 2 * STAGE_B + 1024);
    float* sw   = (float*)(smc + 2 * STAGE_B + 1024 + 2048);

    const int tid = threadIdx.x;
    const int wid = tid >> 5, l = tid & 31;
    const int wy = wid >> 2, wx = wid & 3;
    const int g = l >> 2, c4 = l & 3;
    const int lr = l & 7, sel = l >> 3;
    const int b = blockIdx.z;
    const int i0 = blockIdx.x * 128, o0 = blockIdx.y * 128;

    if (tid < 128) {
        ssum[tid] = 0.f; ssq[tid] = 0.f;
        size_t base = ((size_t)b * NPTS + i0 + tid) * 3;
        sidx[4 * tid] = g_idx3[base]; sidx[4 * tid + 1] = g_idx3[base + 1];
        sidx[4 * tid + 2] = g_idx3[base + 2];
        sw[4 * tid] = g_w3[base]; sw[4 * tid + 1] = g_w3[base + 1];
        sw[4 * tid + 2] = g_w3[base + 2];
    }
    __syncthreads();

    const float* Uf = uf + (size_t)b * CH * NPTS;     // (c, i) f32
    const __half* Bbase = g_W1h + (size_t)o0 * K1;
    const __half* kftb = g_kft + (size_t)b * MPTS * CH;

    float acc[4][4][4];
    #pragma unroll
    for (int mi = 0; mi < 4; mi++)
        #pragma unroll
        for (int ni = 0; ni < 4; ni++)
            #pragma unroll
            for (int t = 0; t < 4; t++) acc[mi][ni][t] = 0.f;

    const int rb = tid >> 3, qq = tid & 7;
    const int NC = K1 / 64;

    uint4 areg[4];

    auto loadB = [&](int c, int s) {
        int k0 = c * 64;
        uint32_t offB = sbase + s * STAGE_B + ATILE_B;
        const __half* Bb = Bbase + k0;
        #pragma unroll
        for (int it = 0; it < 4; it++) {
            int r = rb + it * 32;
            cp16(offB + r * (HS * 2) + qq * 16, Bb + (size_t)r * K1 + qq * 8);
        }
        asm volatile("cp.async.commit_group;" ::: "memory");
    };
    auto ldgA = [&](int c) {
        if (c < 4) {   // interp half: gather + blend
            int k0 = c * 64 + qq * 8;
            #pragma unroll
            for (int it = 0; it < 4; it++) {
                int r = rb + it * 32;
                int4 jj = *(const int4*)&sidx[4 * r];
                float4 ww = *(const float4*)&sw[4 * r];
                union { uint4 u; __half2 h[4]; } A0, A1, A2, R;
                A0.u = *(const uint4*)(kftb + (size_t)jj.x * CH + k0);
                A1.u = *(const uint4*)(kftb + (size_t)jj.y * CH + k0);
                A2.u = *(const uint4*)(kftb + (size_t)jj.z * CH + k0);
                #pragma unroll
                for (int j = 0; j < 4; j++) {
                    float2 a = __half22float2(A0.h[j]);
                    float2 d = __half22float2(A1.h[j]);
                    float2 e = __half22float2(A2.h[j]);
                    R.h[j] = __floats2half2_rn(ww.x * a.x + ww.y * d.x + ww.z * e.x,
                                               ww.x * a.y + ww.y * d.y + ww.z * e.y);
                }
                areg[it] = R.u;
            }
        } else {       // uf half: f32 load + half convert (row = k, 32 i-vals per thread)
            int row = tid >> 2, q = tid & 3;
            const float* src = Uf + (size_t)((c - 4) * 64 + row) * NPTS + i0 + q * 32;
            #pragma unroll
            for (int it = 0; it < 4; it++) {
                float4 v0 = *(const float4*)(src + it * 8);
                float4 v1 = *(const float4*)(src + it * 8 + 4);
                union { uint4 u; __half2 h[4]; } R;
                R.h[0] = __floats2half2_rn(v0.x, v0.y);
                R.h[1] = __floats2half2_rn(v0.z, v0.w);
                R.h[2] = __floats2half2_rn(v1.x, v1.y);
                R.h[3] = __floats2half2_rn(v1.z, v1.w);
                areg[it] = R.u;
            }
        }
    };
    auto stsA = [&](int c, int s) {
        if (c < 4) {
            #pragma unroll
            for (int it = 0; it < 4; it++)
                *(uint4*)(smc + s * STAGE_B + (rb + it * 32) * (HS * 2) + qq * 16) = areg[it];
        } else {
            int row = tid >> 2, q = tid & 3;
            #pragma unroll
            for (int it = 0; it < 4; it++)
                *(uint4*)(smc + s * STAGE_B + row * (RS2H * 2) + q * 64 + it * 16) = areg[it];
        }
    };

    const uint32_t aLane = ((uint32_t)(wy * 64 + lr + ((sel & 1) << 3)) * HS + ((sel >> 1) << 3)) * 2;
    const uint32_t bLane = ((uint32_t)(wx * 32 + lr + ((sel >> 1) << 3)) * HS + ((sel & 1) << 3)) * 2;
    const uint32_t aLaneT = ((uint32_t)(lr + ((sel >> 1) << 3)) * RS2H + (wy * 64 + ((sel & 1) << 3))) * 2;

    ldgA(0); stsA(0, 0); loadB(0, 0);
    ldgA(1); stsA(1, 1); loadB(1, 1);

    for (int c = 0; c < NC; c++) {
        if (c + 1 < NC) {
            asm volatile("cp.async.wait_group 1;" ::: "memory");
        } else {
            asm volatile("cp.async.wait_group 0;" ::: "memory");
        }
        __syncthreads();

        if (c + 2 < NC) ldgA(c + 2);

        uint32_t sA = sbase + (c & 1) * STAGE_B;
        uint32_t sB = sA + ATILE_B;
        if (c < 4) {
            #pragma unroll
            for (int kk16 = 0; kk16 < 4; kk16++) {
                uint32_t koff = kk16 * 32;
                uint32_t af[4][4], bf[4][2];
                #pragma unroll
                for (int mi = 0; mi < 4; mi++)
                    ldm_x4(af[mi], sA + aLane + mi * (16 * HS * 2) + koff);
                #pragma unroll
                for (int nip = 0; nip < 2; nip++) {
                    uint32_t r[4];
                    ldm_x4(r, sB + bLane + nip * (16 * HS * 2) + koff);
                    bf[2 * nip][0] = r[0]; bf[2 * nip][1] = r[1];
                    bf[2 * nip + 1][0] = r[2]; bf[2 * nip + 1][1] = r[3];
                }
                #pragma unroll
                for (int mi = 0; mi < 4; mi++)
                    #pragma unroll
                    for (int ni = 0; ni < 4; ni++)
                        mma_f16(acc[mi][ni], af[mi], bf[ni]);
            }
        } else {
            #pragma unroll
            for (int kk16 = 0; kk16 < 4; kk16++) {
                uint32_t krowoff = kk16 * 16 * (RS2H * 2);
                uint32_t koff = kk16 * 32;
                uint32_t af[4][4], bf[4][2];
                #pragma unroll
                for (int mi = 0; mi < 4; mi++)
                    ldm_x4t(af[mi], sA + aLaneT + krowoff + mi * 32);
                #pragma unroll
                for (int nip = 0; nip < 2; nip++) {
                    uint32_t r[4];
                    ldm_x4(r, sB + bLane + nip * (16 * HS * 2) + koff);
                    bf[2 * nip][0] = r[0]; bf[2 * nip][1] = r[1];
                    bf[2 * nip + 1][0] = r[2]; bf[2 * nip + 1][1] = r[3];
                }
                #pragma unroll
                for (int mi = 0; mi < 4; mi++)
                    #pragma unroll
                    for (int ni = 0; ni < 4; ni++)
                        mma_f16(acc[mi][ni], af[mi], bf[ni]);
            }
        }
        __syncthreads();
        if (c + 2 < NC) {
            int s = (c + 2) & 1;
            stsA(c + 2, s);
            loadB(c + 2, s);
        }
    }

    GEMM_EPILOGUE(Dg);
}

// ---------------- GEMM2: BN1 params inline; BN1+ReLU fused in A-loader ----------------
__global__ void __launch_bounds__(256, 2) gemm2_f(const __half* __restrict__ Ag,
                                                  const __half* __restrict__ Bg,
                                                  __half* __restrict__ Dg,
                                                  const float* __restrict__ ga1,
                                                  const float* __restrict__ be1,
                                                  float* __restrict__ sums,
                                                  float* __restrict__ sqs) {
    extern __shared__ char smc[];
    const uint32_t sbase = smem_u32(smc);
    float* ssum = (float*)(smc + 2 * STAGE_B);
    float* ssq  = ssum + 128;
    __half* s_sc = (__half*)(smc + 2 * STAGE_B + 1024);
    __half* s_sh = s_sc + 256;

    const int tid = threadIdx.x;
    const int wid = tid >> 5, l = tid & 31;
    const int wy = wid >> 2, wx = wid & 3;
    const int g = l >> 2, c4 = l & 3;
    const int lr = l & 7, sel = l >> 3;
    const int b = blockIdx.z;
    const int i0 = blockIdx.x * 128, o0 = blockIdx.y * 128;

    {
        float inv = 1.0f / (float)(BB * NPTS);
        float mean = g_sum1[tid] * inv;
        float var = g_sq1[tid] * inv - mean * mean;
        float sc = ga1[tid] * rsqrtf(var + BN_EPS);
        float sh = be1[tid] - mean * sc;
        s_sc[tid] = __float2half_rn(sc);
        s_sh[tid] = __float2half_rn(sh);
    }
    if (tid < 128) { ssum[tid] = 0.f; ssq[tid] = 0.f; }
    __syncthreads();

    const __half* Abase = Ag + ((size_t)b * NPTS + i0) * CH;
    const __half* Bbase = Bg + (size_t)o0 * CH;

    float acc[4][4][4];
    #pragma unroll
    for (int mi = 0; mi < 4; mi++)
        #pragma unroll
        for (int ni = 0; ni < 4; ni++)
            #pragma unroll
            for (int t = 0; t < 4; t++) acc[mi][ni][t] = 0.f;

    const int rb = tid >> 3, qq = tid & 7;
    const int NC = CH / 64;

    uint4 areg[4], screg, shreg;

    auto loadB = [&](int c, int s) {
        int k0 = c * 64;
        uint32_t offB = sbase + s * STAGE_B + ATILE_B;
        const __half* Bb = Bbase + k0;
        #pragma unroll
        for (int it = 0; it < 4; it++) {
            int r = rb + it * 32;
            cp16(offB + r * (HS * 2) + qq * 16, Bb + (size_t)r * CH + qq * 8);
        }
        asm volatile("cp.async.commit_group;" ::: "memory");
    };
    auto ldgA = [&](int c) {
        int k0 = c * 64;
        #pragma unroll
        for (int it = 0; it < 4; it++)
            areg[it] = *(const uint4*)(Abase + (size_t)(rb + it * 32) * CH + k0 + qq * 8);
        screg = *(const uint4*)(s_sc + k0 + qq * 8);
        shreg = *(const uint4*)(s_sh + k0 + qq * 8);
    };
    auto stsA = [&](int s) {
        const __half2 z2 = __float2half2_rn(0.f);
        union { uint4 u; __half2 h[4]; } sc, sh;
        sc.u = screg; sh.u = shreg;
        #pragma unroll
        for (int it = 0; it < 4; it++) {
            int r = rb + it * 32;
            union { uint4 u; __half2 h[4]; } v;
            v.u = areg[it];
            #pragma unroll
            for (int j = 0; j < 4; j++)
                v.h[j] = __hmax2(__hfma2(v.h[j], sc.h[j], sh.h[j]), z2);
            *(uint4*)(smc + s * STAGE_B + r * (HS * 2) + qq * 16) = v.u;
        }
    };

    const uint32_t aLane = ((uint32_t)(wy * 64 + lr + ((sel & 1) << 3)) * HS + ((sel >> 1) << 3)) * 2;
    const uint32_t bLane = ((uint32_t)(wx * 32 + lr + ((sel >> 1) << 3)) * HS + ((sel & 1) << 3)) * 2;

    ldgA(0); stsA(0); loadB(0, 0);
    ldgA(1); stsA(1); loadB(1, 1);

    for (int c = 0; c < NC; c++) {
        if (c + 1 < NC) {
            asm volatile("cp.async.wait_group 1;" ::: "memory");
        } else {
            asm volatile("cp.async.wait_group 0;" ::: "memory");
        }
        __syncthreads();

        if (c + 2 < NC) ldgA(c + 2);

        uint32_t sA = sbase + (c & 1) * STAGE_B;
        uint32_t sB = sA + ATILE_B;
        #pragma unroll
        for (int kk16 = 0; kk16 < 4; kk16++) {
            uint32_t koff = kk16 * 32;
            uint32_t af[4][4], bf[4][2];
            #pragma unroll
            for (int mi = 0; mi < 4; mi++)
                ldm_x4(af[mi], sA + aLane + mi * (16 * HS * 2) + koff);
            #pragma unroll
            for (int nip = 0; nip < 2; nip++) {
                uint32_t r[4];
                ldm_x4(r, sB + bLane + nip * (16 * HS * 2) + koff);
                bf[2 * nip][0] = r[0]; bf[2 * nip][1] = r[1];
                bf[2 * nip + 1][0] = r[2]; bf[2 * nip + 1][1] = r[3];
            }
            #pragma unroll
            for (int mi = 0; mi < 4; mi++)
                #pragma unroll
                for (int ni = 0; ni < 4; ni++)
                    mma_f16(acc[mi][ni], af[mi], bf[ni]);
        }
        __syncthreads();
        if (c + 2 < NC) {
            int s = (c + 2) & 1;
            stsA(s);
            loadB(c + 2, s);
        }
    }

    GEMM_EPILOGUE(Dg);
}

// ---------------- final: inline BN2 + ReLU + transpose ----------------
__global__ void out_kernel(float* __restrict__ out,
                           const float* __restrict__ ga2, const float* __restrict__ be2) {
    __shared__ float tile[32][33];
    __shared__ float s_sc[32], s_sh[32];
    int b = blockIdx.z, i0 = blockIdx.x * 32, o0 = blockIdx.y * 32;
    int t = threadIdx.y * 32 + threadIdx.x;
    if (t < 32) {
        int o = o0 + t;
        float inv = 1.0f / (float)(BB * NPTS);
        float mean = g_sum2[o] * inv;
        float var = g_sq2[o] * inv - mean * mean;
        float sc = ga2[o] * rsqrtf(var + BN_EPS);
        s_sc[t] = sc;
        s_sh[t] = be2[o] - mean * sc;
    }
    const __half* src = g_Y2h + (size_t)b * NPTS * CH;
    for (int r = threadIdx.y; r < 32; r += 8)
        tile[r][threadIdx.x] = __half2float(src[(size_t)(i0 + r) * CH + o0 + threadIdx.x]);
    __syncthreads();
    float* dst = out + (size_t)b * CH * NPTS;
    for (int r = threadIdx.y; r < 32; r += 8) {
        float v = fmaxf(fmaf(tile[threadIdx.x][r], s_sc[r], s_sh[r]), 0.f);
        dst[(size_t)(o0 + r) * NPTS + i0 + threadIdx.x] = v;
    }
}

// ---------------- launch ----------------
extern "C" void kernel_launch(void* const* d_in, const int* in_sizes, int n_in,
                              void* d_out, int out_size) {
    const float* unknown = (const float*)d_in[0];
    const float* known   = (const float*)d_in[1];
    const float* uf      = (const float*)d_in[2];
    const float* kf      = (const float*)d_in[3];
    const float* W1      = (const float*)d_in[4];
    const float* g1      = (const float*)d_in[5];
    const float* be1     = (const float*)d_in[6];
    const float* W2      = (const float*)d_in[7];
    const float* g2      = (const float*)d_in[8];
    const float* be2     = (const float*)d_in[9];
    float* out = (float*)d_out;

    static cudaStream_t s1 = nullptr, s2 = nullptr;
    static cudaEvent_t ev0 = nullptr, ev1 = nullptr, ev2 = nullptr;
    if (!s1) {
        cudaStreamCreateWithFlags(&s1, cudaStreamNonBlocking);
        cudaStreamCreateWithFlags(&s2, cudaStreamNonBlocking);
        cudaEventCreateWithFlags(&ev0, cudaEventDisableTiming);
        cudaEventCreateWithFlags(&ev1, cudaEventDisableTiming);
        cudaEventCreateWithFlags(&ev2, cudaEventDisableTiming);
        cudaFuncSetAttribute(gemm1_f, cudaFuncAttributeMaxDynamicSharedMemorySize, GEMM1_SMEM);
        cudaFuncSetAttribute(gemm2_f, cudaFuncAttributeMaxDynamicSharedMemorySize, GEMM2_SMEM);
    }

    __half *pHh, *pY2h, *pW2h;
    float *ps1, *pq1, *ps2, *pq2;
    cudaGetSymbolAddress((void**)&pHh, g_Hh);
    cudaGetSymbolAddress((void**)&pY2h, g_Y2h);
    cudaGetSymbolAddress((void**)&pW2h, g_W2h);
    cudaGetSymbolAddress((void**)&ps1, g_sum1);
    cudaGetSymbolAddress((void**)&pq1, g_sq1);
    cudaGetSymbolAddress((void**)&ps2, g_sum2);
    cudaGetSymbolAddress((void**)&pq2, g_sq2);

    cudaEventRecord(ev0, 0);
    cudaStreamWaitEvent(s1, ev0, 0);
    cudaStreamWaitEvent(s2, ev0, 0);

    nn_kernel<<<dim3(NPTS / 256, BB), 256>>>(unknown, known);
    kft_kernel<<<dim3(MPTS / 32, CH / 32, BB), dim3(32, 8), 0, s1>>>(kf);
    prep_kernel<<<CH * K1 / 256 + CH * CH / 256 + 1, 256, 0, s2>>>(W1, W2);

    cudaEventRecord(ev1, s1);
    cudaEventRecord(ev2, s2);
    cudaStreamWaitEvent(0, ev1, 0);
    cudaStreamWaitEvent(0, ev2, 0);

    gemm1_f<<<dim3(NPTS / 128, CH / 128, BB), 256, GEMM1_SMEM>>>(uf, pHh, ps1, pq1);
    gemm2_f<<<dim3(NPTS / 128, CH / 128, BB), 256, GEMM2_SMEM>>>(pHh, pW2h, pY2h, g1, be1, ps2, pq2);
    out_kernel<<<dim3(NPTS / 32, CH / 32, BB), dim3(32, 8)>>>(out, g2, be2);
}

// round 15
// speedup vs baseline: 1.2075x; 1.2075x over previous
#include <cuda_runtime.h>
#include <cuda_fp16.h>
#include <cstdint>

#define BB   16
#define NPTS 4096
#define MPTS 1024
#define CH   256
#define K1   512
#define BN_EPS 1e-5f

// ---------------- scratch ----------------
__device__ __align__(16) __half g_kft[(size_t)BB * MPTS * CH];
__device__ __align__(16) __half g_Xc[(size_t)BB * CH * NPTS];
__device__ __align__(16) __half g_Hh[(size_t)BB * NPTS * CH];
__device__ __align__(16) __half g_Y2h[(size_t)BB * NPTS * CH];
__device__ __align__(16) __half g_W1h[CH * K1];
__device__ __align__(16) __half g_W2h[CH * CH];
__device__ int   g_idx3[BB * NPTS * 3];
__device__ float g_w3[BB * NPTS * 3];
__device__ float g_sum1[CH], g_sq1[CH], g_sum2[CH], g_sq2[CH];

// ---------------- helpers ----------------
__device__ __forceinline__ void cp16(uint32_t saddr, const void* g) {
    asm volatile("cp.async.ca.shared.global [%0], [%1], 16;" :: "r"(saddr), "l"(g));
}
__device__ __forceinline__ uint32_t smem_u32(const void* p) {
    uint32_t a;
    asm("{ .reg .u64 t; cvta.to.shared.u64 t, %1; cvt.u32.u64 %0, t; }" : "=r"(a) : "l"(p));
    return a;
}
__device__ __forceinline__ void ldm_x4(uint32_t* r, uint32_t addr) {
    asm volatile("ldmatrix.sync.aligned.m8n8.x4.shared.b16 {%0,%1,%2,%3}, [%4];"
                 : "=r"(r[0]), "=r"(r[1]), "=r"(r[2]), "=r"(r[3]) : "r"(addr));
}
__device__ __forceinline__ void ldm_x4t(uint32_t* r, uint32_t addr) {
    asm volatile("ldmatrix.sync.aligned.m8n8.x4.trans.shared.b16 {%0,%1,%2,%3}, [%4];"
                 : "=r"(r[0]), "=r"(r[1]), "=r"(r[2]), "=r"(r[3]) : "r"(addr));
}
__device__ __forceinline__ void mma_f16(float* d, const uint32_t* a, const uint32_t* b) {
    asm volatile(
        "mma.sync.aligned.m16n8k16.row.col.f32.f16.f16.f32 "
        "{%0,%1,%2,%3}, {%4,%5,%6,%7}, {%8,%9}, {%0,%1,%2,%3};"
        : "+f"(d[0]), "+f"(d[1]), "+f"(d[2]), "+f"(d[3])
        : "r"(a[0]), "r"(a[1]), "r"(a[2]), "r"(a[3]), "r"(b[0]), "r"(b[1]));
}

// ---------------- prep ----------------
__global__ void prep_kernel(const float* __restrict__ W1, const float* __restrict__ W2) {
    int blk = blockIdx.x;
    int t = threadIdx.x;
    if (blk < CH * K1 / 256) {
        int i = blk * 256 + t;
        g_W1h[i] = __float2half_rn(W1[i]);
    } else if (blk < CH * K1 / 256 + CH * CH / 256) {
        int i = (blk - CH * K1 / 256) * 256 + t;
        g_W2h[i] = __float2half_rn(W2[i]);
    } else {
        g_sum1[t] = 0.f; g_sq1[t] = 0.f; g_sum2[t] = 0.f; g_sq2[t] = 0.f;
    }
}

// ---------------- uf f32 -> half ----------------
__global__ void cvt_kernel(const float* __restrict__ uf) {
    size_t q = (size_t)blockIdx.x * 256 + threadIdx.x;
    float4 v = ((const float4*)uf)[q];
    union { __half2 h[2]; uint2 u; } cv;
    cv.h[0] = __floats2half2_rn(v.x, v.y);
    cv.h[1] = __floats2half2_rn(v.z, v.w);
    *(uint2*)(g_Xc + q * 4) = cv.u;
}

// ---------------- 3-NN + weights ----------------
__global__ void nn_kernel(const float* __restrict__ unknown, const float* __restrict__ known) {
    __shared__ float4 sk[MPTS];
    int b = blockIdx.y;
    const float* kb = known + (size_t)b * MPTS * 3;
    for (int j = threadIdx.x; j < MPTS; j += blockDim.x) {
        float kx = kb[j * 3 + 0], ky = kb[j * 3 + 1], kz = kb[j * 3 + 2];
        sk[j] = make_float4(kx, ky, kz, kx * kx + ky * ky + kz * kz);
    }
    __syncthreads();
    int i = blockIdx.x * blockDim.x + threadIdx.x;
    const float* u = unknown + ((size_t)b * NPTS + i) * 3;
    float ux = u[0], uy = u[1], uz = u[2];
    float ax = -2.f * ux, ay = -2.f * uy, az = -2.f * uz;
    float b0 = 3.4e38f, b1 = 3.4e38f, b2 = 3.4e38f;
    int i0 = 0, i1 = 0, i2 = 0;
    #pragma unroll 4
    for (int j = 0; j < MPTS; j++) {
        float4 k4 = sk[j];
        float s = fmaf(k4.x, ax, fmaf(k4.y, ay, fmaf(k4.z, az, k4.w)));
        if (s < b2) {
            if (s < b1) {
                if (s < b0) { b2 = b1; i2 = i1; b1 = b0; i1 = i0; b0 = s; i0 = j; }
                else        { b2 = b1; i2 = i1; b1 = s;  i1 = j; }
            } else          { b2 = s;  i2 = j; }
        }
    }
    float4 k0 = sk[i0], k1 = sk[i1], k2 = sk[i2];
    float d0 = (ux - k0.x) * (ux - k0.x) + (uy - k0.y) * (uy - k0.y) + (uz - k0.z) * (uz - k0.z);
    float d1 = (ux - k1.x) * (ux - k1.x) + (uy - k1.y) * (uy - k1.y) + (uz - k1.z) * (uz - k1.z);
    float d2 = (ux - k2.x) * (ux - k2.x) + (uy - k2.y) * (uy - k2.y) + (uz - k2.z) * (uz - k2.z);
    float r0 = 1.0f / (d0 + 1e-8f), r1 = 1.0f / (d1 + 1e-8f), r2 = 1.0f / (d2 + 1e-8f);
    float inv = 1.0f / (r0 + r1 + r2);
    size_t base = ((size_t)b * NPTS + i) * 3;
    g_idx3[base] = i0; g_idx3[base + 1] = i1; g_idx3[base + 2] = i2;
    g_w3[base] = r0 * inv; g_w3[base + 1] = r1 * inv; g_w3[base + 2] = r2 * inv;
}

// ---------------- known_feats transpose ----------------
__global__ void kft_kernel(const float* __restrict__ kf) {
    __shared__ float tile[32][33];
    int b = blockIdx.z, c0 = blockIdx.y * 32, j0 = blockIdx.x * 32;
    const float* src = kf + (size_t)b * CH * MPTS;
    for (int r = threadIdx.y; r < 32; r += 8)
        tile[r][threadIdx.x] = src[(size_t)(c0 + r) * MPTS + j0 + threadIdx.x];
    __syncthreads();
    __half* dst = g_kft + (size_t)b * MPTS * CH;
    for (int r = threadIdx.y; r < 32; r += 8)
        dst[(size_t)(j0 + r) * CH + c0 + threadIdx.x] = __float2half_rn(tile[threadIdx.x][r]);
}

// ---------------- GEMM geometry (2-stage, 2 blocks/SM) ----------------
#define HS      72
#define RS2H    136
#define ATILE_B (128 * HS * 2)
#define STAGE_B (2 * ATILE_B)
#define GEMM1_SMEM (2 * STAGE_B + 1024 + 4096)
#define GEMM2_SMEM (2 * STAGE_B + 2048)

// ---------------- direct-store epilogue + stats ----------------
#define GEMM_EPILOGUE(Dg)                                                              \
    do {                                                                               \
        _Pragma("unroll")                                                              \
        for (int mi = 0; mi < 4; mi++) {                                               \
            int row0 = i0 + wy * 64 + mi * 16 + g;                                     \
            _Pragma("unroll")                                                          \
            for (int ni = 0; ni < 4; ni++) {                                           \
                int col = o0 + wx * 32 + ni * 8 + 2 * c4;                              \
                *(__half2*)((Dg) + ((size_t)b * NPTS + row0) * CH + col) =             \
                    __floats2half2_rn(acc[mi][ni][0], acc[mi][ni][1]);                 \
                *(__half2*)((Dg) + ((size_t)b * NPTS + row0 + 8) * CH + col) =         \
                    __floats2half2_rn(acc[mi][ni][2], acc[mi][ni][3]);                 \
            }                                                                          \
        }                                                                              \
        _Pragma("unroll")                                                              \
        for (int ni = 0; ni < 4; ni++) {                                               \
            float s0 = 0.f, s1 = 0.f, q0 = 0.f, q1 = 0.f;                              \
            _Pragma("unroll")                                                          \
            for (int mi = 0; mi < 4; mi++) {                                           \
                const float* a = acc[mi][ni];                                          \
                s0 += a[0] + a[2]; s1 += a[1] + a[3];                                  \
                q0 += a[0] * a[0] + a[2] * a[2];                                       \
                q1 += a[1] * a[1] + a[3] * a[3];                                       \
            }                                                                          \
            int lc = wx * 32 + ni * 8 + 2 * c4;                                        \
            atomicAdd(&ssum[lc], s0); atomicAdd(&ssum[lc + 1], s1);                    \
            atomicAdd(&ssq[lc], q0);  atomicAdd(&ssq[lc + 1], q1);                     \
        }                                                                              \
        __syncthreads();                                                               \
        if (tid < 128) {                                                               \
            atomicAdd(&sums[o0 + tid], ssum[tid]);                                     \
            atomicAdd(&sqs[o0 + tid], ssq[tid]);                                       \
        }                                                                              \
    } while (0)

// ---------------- GEMM1: A = [3NN-interp(kft) | uf-trans], B = W1h ----------------
__global__ void __launch_bounds__(256, 2) gemm1_f(__half* __restrict__ Dg,
                                                  float* __restrict__ sums,
                                                  float* __restrict__ sqs) {
    extern __shared__ char smc[];
    const uint32_t sbase = smem_u32(smc);
    float* ssum = (float*)(smc + 2 * STAGE_B);
    float* ssq  = ssum + 128;
    int*   sidx = (int*)(smc + 2 * STAGE_B + 1024);
    float* sw   = (float*)(smc + 2 * STAGE_B + 1024 + 2048);

    const int tid = threadIdx.x;
    const int wid = tid >> 5, l = tid & 31;
    const int wy = wid >> 2, wx = wid & 3;
    const int g = l >> 2, c4 = l & 3;
    const int lr = l & 7, sel = l >> 3;
    const int b = blockIdx.z;
    const int i0 = blockIdx.x * 128, o0 = blockIdx.y * 128;

    if (tid < 128) {
        ssum[tid] = 0.f; ssq[tid] = 0.f;
        size_t base = ((size_t)b * NPTS + i0 + tid) * 3;
        sidx[4 * tid] = g_idx3[base]; sidx[4 * tid + 1] = g_idx3[base + 1];
        sidx[4 * tid + 2] = g_idx3[base + 2];
        sw[4 * tid] = g_w3[base]; sw[4 * tid + 1] = g_w3[base + 1];
        sw[4 * tid + 2] = g_w3[base + 2];
    }
    __syncthreads();

    const __half* Xc = g_Xc + (size_t)b * CH * NPTS;
    const __half* Bbase = g_W1h + (size_t)o0 * K1;
    const __half* kftb = g_kft + (size_t)b * MPTS * CH;

    float acc[4][4][4];
    #pragma unroll
    for (int mi = 0; mi < 4; mi++)
        #pragma unroll
        for (int ni = 0; ni < 4; ni++)
            #pragma unroll
            for (int t = 0; t < 4; t++) acc[mi][ni][t] = 0.f;

    const int rb = tid >> 3, qq = tid & 7;
    const int NC = K1 / 64;

    uint4 areg[4];

    auto loadB = [&](int c, int s) {
        int k0 = c * 64;
        uint32_t offB = sbase + s * STAGE_B + ATILE_B;
        const __half* Bb = Bbase + k0;
        #pragma unroll
        for (int it = 0; it < 4; it++) {
            int r = rb + it * 32;
            cp16(offB + r * (HS * 2) + qq * 16, Bb + (size_t)r * K1 + qq * 8);
        }
        asm volatile("cp.async.commit_group;" ::: "memory");
    };
    auto ldgA = [&](int c) {
        int k0 = c * 64 + qq * 8;
        #pragma unroll
        for (int it = 0; it < 4; it++) {
            int r = rb + it * 32;
            int4 jj = *(const int4*)&sidx[4 * r];
            float4 ww = *(const float4*)&sw[4 * r];
            union { uint4 u; __half2 h[4]; } A0, A1, A2, R;
            A0.u = *(const uint4*)(kftb + (size_t)jj.x * CH + k0);
            A1.u = *(const uint4*)(kftb + (size_t)jj.y * CH + k0);
            A2.u = *(const uint4*)(kftb + (size_t)jj.z * CH + k0);
            #pragma unroll
            for (int j = 0; j < 4; j++) {
                float2 a = __half22float2(A0.h[j]);
                float2 d = __half22float2(A1.h[j]);
                float2 e = __half22float2(A2.h[j]);
                R.h[j] = __floats2half2_rn(ww.x * a.x + ww.y * d.x + ww.z * e.x,
                                           ww.x * a.y + ww.y * d.y + ww.z * e.y);
            }
            areg[it] = R.u;
        }
    };
    auto stsA = [&](int s) {
        #pragma unroll
        for (int it = 0; it < 4; it++)
            *(uint4*)(smc + s * STAGE_B + (rb + it * 32) * (HS * 2) + qq * 16) = areg[it];
    };
    auto loadAuf = [&](int c, int s) {
        int chb = (c - 4) * 64;
        uint32_t offA = sbase + s * STAGE_B;
        #pragma unroll
        for (int it = 0; it < 4; it++) {
            int idx = tid + it * 256;
            int row = idx >> 4;
            int off = idx & 15;
            cp16(offA + row * (RS2H * 2) + off * 16,
                 Xc + (size_t)(chb + row) * NPTS + i0 + off * 8);
        }
    };

    const uint32_t aLane = ((uint32_t)(wy * 64 + lr + ((sel & 1) << 3)) * HS + ((sel >> 1) << 3)) * 2;
    const uint32_t bLane = ((uint32_t)(wx * 32 + lr + ((sel >> 1) << 3)) * HS + ((sel & 1) << 3)) * 2;
    const uint32_t aLaneT = ((uint32_t)(lr + ((sel >> 1) << 3)) * RS2H + (wy * 64 + ((sel & 1) << 3))) * 2;

    ldgA(0); stsA(0); loadB(0, 0);
    ldgA(1); stsA(1); loadB(1, 1);

    for (int c = 0; c < NC; c++) {
        if (c + 1 < NC) {
            asm volatile("cp.async.wait_group 1;" ::: "memory");
        } else {
            asm volatile("cp.async.wait_group 0;" ::: "memory");
        }
        __syncthreads();

        if (c + 2 < 4) ldgA(c + 2);

        uint32_t sA = sbase + (c & 1) * STAGE_B;
        uint32_t sB = sA + ATILE_B;
        if (c < 4) {
            #pragma unroll
            for (int kk16 = 0; kk16 < 4; kk16++) {
                uint32_t koff = kk16 * 32;
                uint32_t af[4][4], bf[4][2];
                #pragma unroll
                for (int mi = 0; mi < 4; mi++)
                    ldm_x4(af[mi], sA + aLane + mi * (16 * HS * 2) + koff);
                #pragma unroll
                for (int nip = 0; nip < 2; nip++) {
                    uint32_t r[4];
                    ldm_x4(r, sB + bLane + nip * (16 * HS * 2) + koff);
                    bf[2 * nip][0] = r[0]; bf[2 * nip][1] = r[1];
                    bf[2 * nip + 1][0] = r[2]; bf[2 * nip + 1][1] = r[3];
                }
                #pragma unroll
                for (int mi = 0; mi < 4; mi++)
                    #pragma unroll
                    for (int ni = 0; ni < 4; ni++)
                        mma_f16(acc[mi][ni], af[mi], bf[ni]);
            }
        } else {
            #pragma unroll
            for (int kk16 = 0; kk16 < 4; kk16++) {
                uint32_t krowoff = kk16 * 16 * (RS2H * 2);
                uint32_t koff = kk16 * 32;
                uint32_t af[4][4], bf[4][2];
                #pragma unroll
                for (int mi = 0; mi < 4; mi++)
                    ldm_x4t(af[mi], sA + aLaneT + krowoff + mi * 32);
                #pragma unroll
                for (int nip = 0; nip < 2; nip++) {
                    uint32_t r[4];
                    ldm_x4(r, sB + bLane + nip * (16 * HS * 2) + koff);
                    bf[2 * nip][0] = r[0]; bf[2 * nip][1] = r[1];
                    bf[2 * nip + 1][0] = r[2]; bf[2 * nip + 1][1] = r[3];
                }
                #pragma unroll
                for (int mi = 0; mi < 4; mi++)
                    #pragma unroll
                    for (int ni = 0; ni < 4; ni++)
                        mma_f16(acc[mi][ni], af[mi], bf[ni]);
            }
        }
        __syncthreads();
        if (c + 2 < NC) {
            int s = (c + 2) & 1;
            if (c + 2 < 4) { stsA(s); } else { loadAuf(c + 2, s); }
            loadB(c + 2, s);
        }
    }

    GEMM_EPILOGUE(Dg);
}

// ---------------- GEMM2: BN1 params inline; BN1+ReLU fused in A-loader ----------------
__global__ void __launch_bounds__(256, 2) gemm2_f(const __half* __restrict__ Ag,
                                                  const __half* __restrict__ Bg,
                                                  __half* __restrict__ Dg,
                                                  const float* __restrict__ ga1,
                                                  const float* __restrict__ be1,
                                                  float* __restrict__ sums,
                                                  float* __restrict__ sqs) {
    extern __shared__ char smc[];
    const uint32_t sbase = smem_u32(smc);
    float* ssum = (float*)(smc + 2 * STAGE_B);
    float* ssq  = ssum + 128;
    __half* s_sc = (__half*)(smc + 2 * STAGE_B + 1024);
    __half* s_sh = s_sc + 256;

    const int tid = threadIdx.x;
    const int wid = tid >> 5, l = tid & 31;
    const int wy = wid >> 2, wx = wid & 3;
    const int g = l >> 2, c4 = l & 3;
    const int lr = l & 7, sel = l >> 3;
    const int b = blockIdx.z;
    const int i0 = blockIdx.x * 128, o0 = blockIdx.y * 128;

    {
        float inv = 1.0f / (float)(BB * NPTS);
        float mean = g_sum1[tid] * inv;
        float var = g_sq1[tid] * inv - mean * mean;
        float sc = ga1[tid] * rsqrtf(var + BN_EPS);
        float sh = be1[tid] - mean * sc;
        s_sc[tid] = __float2half_rn(sc);
        s_sh[tid] = __float2half_rn(sh);
    }
    if (tid < 128) { ssum[tid] = 0.f; ssq[tid] = 0.f; }
    __syncthreads();

    const __half* Abase = Ag + ((size_t)b * NPTS + i0) * CH;
    const __half* Bbase = Bg + (size_t)o0 * CH;

    float acc[4][4][4];
    #pragma unroll
    for (int mi = 0; mi < 4; mi++)
        #pragma unroll
        for (int ni = 0; ni < 4; ni++)
            #pragma unroll
            for (int t = 0; t < 4; t++) acc[mi][ni][t] = 0.f;

    const int rb = tid >> 3, qq = tid & 7;
    const int NC = CH / 64;

    uint4 areg[4], screg, shreg;

    auto loadB = [&](int c, int s) {
        int k0 = c * 64;
        uint32_t offB = sbase + s * STAGE_B + ATILE_B;
        const __half* Bb = Bbase + k0;
        #pragma unroll
        for (int it = 0; it < 4; it++) {
            int r = rb + it * 32;
            cp16(offB + r * (HS * 2) + qq * 16, Bb + (size_t)r * CH + qq * 8);
        }
        asm volatile("cp.async.commit_group;" ::: "memory");
    };
    auto ldgA = [&](int c) {
        int k0 = c * 64;
        #pragma unroll
        for (int it = 0; it < 4; it++)
            areg[it] = *(const uint4*)(Abase + (size_t)(rb + it * 32) * CH + k0 + qq * 8);
        screg = *(const uint4*)(s_sc + k0 + qq * 8);
        shreg = *(const uint4*)(s_sh + k0 + qq * 8);
    };
    auto stsA = [&](int s) {
        const __half2 z2 = __float2half2_rn(0.f);
        union { uint4 u; __half2 h[4]; } sc, sh;
        sc.u = screg; sh.u = shreg;
        #pragma unroll
        for (int it = 0; it < 4; it++) {
            int r = rb + it * 32;
            union { uint4 u; __half2 h[4]; } v;
            v.u = areg[it];
            #pragma unroll
            for (int j = 0; j < 4; j++)
                v.h[j] = __hmax2(__hfma2(v.h[j], sc.h[j], sh.h[j]), z2);
            *(uint4*)(smc + s * STAGE_B + r * (HS * 2) + qq * 16) = v.u;
        }
    };

    const uint32_t aLane = ((uint32_t)(wy * 64 + lr + ((sel & 1) << 3)) * HS + ((sel >> 1) << 3)) * 2;
    const uint32_t bLane = ((uint32_t)(wx * 32 + lr + ((sel >> 1) << 3)) * HS + ((sel & 1) << 3)) * 2;

    ldgA(0); stsA(0); loadB(0, 0);
    ldgA(1); stsA(1); loadB(1, 1);

    for (int c = 0; c < NC; c++) {
        if (c + 1 < NC) {
            asm volatile("cp.async.wait_group 1;" ::: "memory");
        } else {
            asm volatile("cp.async.wait_group 0;" ::: "memory");
        }
        __syncthreads();

        if (c + 2 < NC) ldgA(c + 2);

        uint32_t sA = sbase + (c & 1) * STAGE_B;
        uint32_t sB = sA + ATILE_B;
        #pragma unroll
        for (int kk16 = 0; kk16 < 4; kk16++) {
            uint32_t koff = kk16 * 32;
            uint32_t af[4][4], bf[4][2];
            #pragma unroll
            for (int mi = 0; mi < 4; mi++)
                ldm_x4(af[mi], sA + aLane + mi * (16 * HS * 2) + koff);
            #pragma unroll
            for (int nip = 0; nip < 2; nip++) {
                uint32_t r[4];
                ldm_x4(r, sB + bLane + nip * (16 * HS * 2) + koff);
                bf[2 * nip][0] = r[0]; bf[2 * nip][1] = r[1];
                bf[2 * nip + 1][0] = r[2]; bf[2 * nip + 1][1] = r[3];
            }
            #pragma unroll
            for (int mi = 0; mi < 4; mi++)
                #pragma unroll
                for (int ni = 0; ni < 4; ni++)
                    mma_f16(acc[mi][ni], af[mi], bf[ni]);
        }
        __syncthreads();
        if (c + 2 < NC) {
            int s = (c + 2) & 1;
            stsA(s);
            loadB(c + 2, s);
        }
    }

    GEMM_EPILOGUE(Dg);
}

// ---------------- final: inline BN2 + ReLU + transpose (64-o x 32-i tiles, half2 loads) ----------------
__global__ void out_kernel(float* __restrict__ out,
                           const float* __restrict__ ga2, const float* __restrict__ be2) {
    __shared__ float tile[64][33];
    __shared__ float s_sc[64], s_sh[64];
    int b = blockIdx.z, i0 = blockIdx.x * 32, o0 = blockIdx.y * 64;
    int tx = threadIdx.x, ty = threadIdx.y;
    int t = ty * 32 + tx;
    if (t < 64) {
        int o = o0 + t;
        float inv = 1.0f / (float)(BB * NPTS);
        float mean = g_sum2[o] * inv;
        float var = g_sq2[o] * inv - mean * mean;
        float sc = ga2[o] * rsqrtf(var + BN_EPS);
        s_sc[t] = sc;
        s_sh[t] = be2[o] - mean * sc;
    }
    const __half* src = g_Y2h + (size_t)b * NPTS * CH;
    for (int r = ty; r < 32; r += 8) {
        __half2 v = *(const __half2*)(src + (size_t)(i0 + r) * CH + o0 + 2 * tx);
        float2 f = __half22float2(v);
        tile[2 * tx][r] = f.x;
        tile[2 * tx + 1][r] = f.y;
    }
    __syncthreads();
    float* dst = out + (size_t)b * CH * NPTS;
    for (int r = ty; r < 64; r += 8) {
        float v = fmaxf(fmaf(tile[r][tx], s_sc[r], s_sh[r]), 0.f);
        dst[(size_t)(o0 + r) * NPTS + i0 + tx] = v;
    }
}

// ---------------- launch ----------------
extern "C" void kernel_launch(void* const* d_in, const int* in_sizes, int n_in,
                              void* d_out, int out_size) {
    const float* unknown = (const float*)d_in[0];
    const float* known   = (const float*)d_in[1];
    const float* uf      = (const float*)d_in[2];
    const float* kf      = (const float*)d_in[3];
    const float* W1      = (const float*)d_in[4];
    const float* g1      = (const float*)d_in[5];
    const float* be1     = (const float*)d_in[6];
    const float* W2      = (const float*)d_in[7];
    const float* g2      = (const float*)d_in[8];
    const float* be2     = (const float*)d_in[9];
    float* out = (float*)d_out;

    static cudaStream_t s1 = nullptr, s2 = nullptr;
    static cudaEvent_t ev0 = nullptr, ev1 = nullptr, ev2 = nullptr;
    if (!s1) {
        cudaStreamCreateWithFlags(&s1, cudaStreamNonBlocking);
        cudaStreamCreateWithFlags(&s2, cudaStreamNonBlocking);
        cudaEventCreateWithFlags(&ev0, cudaEventDisableTiming);
        cudaEventCreateWithFlags(&ev1, cudaEventDisableTiming);
        cudaEventCreateWithFlags(&ev2, cudaEventDisableTiming);
        cudaFuncSetAttribute(gemm1_f, cudaFuncAttributeMaxDynamicSharedMemorySize, GEMM1_SMEM);
        cudaFuncSetAttribute(gemm2_f, cudaFuncAttributeMaxDynamicSharedMemorySize, GEMM2_SMEM);
    }

    __half *pHh, *pY2h, *pW2h;
    float *ps1, *pq1, *ps2, *pq2;
    cudaGetSymbolAddress((void**)&pHh, g_Hh);
    cudaGetSymbolAddress((void**)&pY2h, g_Y2h);
    cudaGetSymbolAddress((void**)&pW2h, g_W2h);
    cudaGetSymbolAddress((void**)&ps1, g_sum1);
    cudaGetSymbolAddress((void**)&pq1, g_sq1);
    cudaGetSymbolAddress((void**)&ps2, g_sum2);
    cudaGetSymbolAddress((void**)&pq2, g_sq2);

    cudaEventRecord(ev0, 0);
    cudaStreamWaitEvent(s1, ev0, 0);
    cudaStreamWaitEvent(s2, ev0, 0);

    nn_kernel<<<dim3(NPTS / 256, BB), 256>>>(unknown, known);
    kft_kernel<<<dim3(MPTS / 32, CH / 32, BB), dim3(32, 8), 0, s1>>>(kf);
    prep_kernel<<<CH * K1 / 256 + CH * CH / 256 + 1, 256, 0, s2>>>(W1, W2);
    cvt_kernel<<<(int)(((size_t)BB * CH * NPTS / 4) / 256), 256, 0, s2>>>(uf);

    cudaEventRecord(ev1, s1);
    cudaEventRecord(ev2, s2);
    cudaStreamWaitEvent(0, ev1, 0);
    cudaStreamWaitEvent(0, ev2, 0);

    gemm1_f<<<dim3(NPTS / 128, CH / 128, BB), 256, GEMM1_SMEM>>>(pHh, ps1, pq1);
    gemm2_f<<<dim3(NPTS / 128, CH / 128, BB), 256, GEMM2_SMEM>>>(pHh, pW2h, pY2h, g1, be1, ps2, pq2);
    out_kernel<<<dim3(NPTS / 32, CH / 64, BB), dim3(32, 8)>>>(out, g2, be2);
}

// round 16
// speedup vs baseline: 1.3980x; 1.1578x over previous
#include <cuda_runtime.h>
#include <cuda_fp16.h>
#include <cstdint>

#define BB   16
#define NPTS 4096
#define MPTS 1024
#define CH   256
#define K1   512
#define BN_EPS 1e-5f

// ---------------- scratch ----------------
__device__ __align__(16) __half g_kft[(size_t)BB * MPTS * CH];
__device__ __align__(16) __half g_Xc[(size_t)BB * CH * NPTS];
__device__ __align__(16) __half g_Hh[(size_t)BB * NPTS * CH];   // conv1 out (b,i,o)
__device__ __align__(16) __half g_Y2t[(size_t)BB * CH * NPTS];  // conv2 out (b,o,i)
__device__ __align__(16) __half g_W1h[CH * K1];
__device__ __align__(16) __half g_W2h[CH * CH];
__device__ int   g_idx3[BB * NPTS * 3];
__device__ float g_w3[BB * NPTS * 3];
__device__ float g_sum1[CH], g_sq1[CH], g_sum2[CH], g_sq2[CH];

// ---------------- helpers ----------------
__device__ __forceinline__ void cp16(uint32_t saddr, const void* g) {
    asm volatile("cp.async.ca.shared.global [%0], [%1], 16;" :: "r"(saddr), "l"(g));
}
__device__ __forceinline__ uint32_t smem_u32(const void* p) {
    uint32_t a;
    asm("{ .reg .u64 t; cvta.to.shared.u64 t, %1; cvt.u32.u64 %0, t; }" : "=r"(a) : "l"(p));
    return a;
}
__device__ __forceinline__ void ldm_x4(uint32_t* r, uint32_t addr) {
    asm volatile("ldmatrix.sync.aligned.m8n8.x4.shared.b16 {%0,%1,%2,%3}, [%4];"
                 : "=r"(r[0]), "=r"(r[1]), "=r"(r[2]), "=r"(r[3]) : "r"(addr));
}
__device__ __forceinline__ void ldm_x4t(uint32_t* r, uint32_t addr) {
    asm volatile("ldmatrix.sync.aligned.m8n8.x4.trans.shared.b16 {%0,%1,%2,%3}, [%4];"
                 : "=r"(r[0]), "=r"(r[1]), "=r"(r[2]), "=r"(r[3]) : "r"(addr));
}
__device__ __forceinline__ void mma_f16(float* d, const uint32_t* a, const uint32_t* b) {
    asm volatile(
        "mma.sync.aligned.m16n8k16.row.col.f32.f16.f16.f32 "
        "{%0,%1,%2,%3}, {%4,%5,%6,%7}, {%8,%9}, {%0,%1,%2,%3};"
        : "+f"(d[0]), "+f"(d[1]), "+f"(d[2]), "+f"(d[3])
        : "r"(a[0]), "r"(a[1]), "r"(a[2]), "r"(a[3]), "r"(b[0]), "r"(b[1]));
}

// ---------------- prep ----------------
__global__ void prep_kernel(const float* __restrict__ W1, const float* __restrict__ W2) {
    int blk = blockIdx.x;
    int t = threadIdx.x;
    if (blk < CH * K1 / 256) {
        int i = blk * 256 + t;
        g_W1h[i] = __float2half_rn(W1[i]);
    } else if (blk < CH * K1 / 256 + CH * CH / 256) {
        int i = (blk - CH * K1 / 256) * 256 + t;
        g_W2h[i] = __float2half_rn(W2[i]);
    } else {
        g_sum1[t] = 0.f; g_sq1[t] = 0.f; g_sum2[t] = 0.f; g_sq2[t] = 0.f;
    }
}

// ---------------- uf f32 -> half ----------------
__global__ void cvt_kernel(const float* __restrict__ uf) {
    size_t q = (size_t)blockIdx.x * 256 + threadIdx.x;
    float4 v = ((const float4*)uf)[q];
    union { __half2 h[2]; uint2 u; } cv;
    cv.h[0] = __floats2half2_rn(v.x, v.y);
    cv.h[1] = __floats2half2_rn(v.z, v.w);
    *(uint2*)(g_Xc + q * 4) = cv.u;
}

// ---------------- 3-NN + weights ----------------
__global__ void nn_kernel(const float* __restrict__ unknown, const float* __restrict__ known) {
    __shared__ float4 sk[MPTS];
    int b = blockIdx.y;
    const float* kb = known + (size_t)b * MPTS * 3;
    for (int j = threadIdx.x; j < MPTS; j += blockDim.x) {
        float kx = kb[j * 3 + 0], ky = kb[j * 3 + 1], kz = kb[j * 3 + 2];
        sk[j] = make_float4(kx, ky, kz, kx * kx + ky * ky + kz * kz);
    }
    __syncthreads();
    int i = blockIdx.x * blockDim.x + threadIdx.x;
    const float* u = unknown + ((size_t)b * NPTS + i) * 3;
    float ux = u[0], uy = u[1], uz = u[2];
    float ax = -2.f * ux, ay = -2.f * uy, az = -2.f * uz;
    float b0 = 3.4e38f, b1 = 3.4e38f, b2 = 3.4e38f;
    int i0 = 0, i1 = 0, i2 = 0;
    #pragma unroll 4
    for (int j = 0; j < MPTS; j++) {
        float4 k4 = sk[j];
        float s = fmaf(k4.x, ax, fmaf(k4.y, ay, fmaf(k4.z, az, k4.w)));
        if (s < b2) {
            if (s < b1) {
                if (s < b0) { b2 = b1; i2 = i1; b1 = b0; i1 = i0; b0 = s; i0 = j; }
                else        { b2 = b1; i2 = i1; b1 = s;  i1 = j; }
            } else          { b2 = s;  i2 = j; }
        }
    }
    float4 k0 = sk[i0], k1 = sk[i1], k2 = sk[i2];
    float d0 = (ux - k0.x) * (ux - k0.x) + (uy - k0.y) * (uy - k0.y) + (uz - k0.z) * (uz - k0.z);
    float d1 = (ux - k1.x) * (ux - k1.x) + (uy - k1.y) * (uy - k1.y) + (uz - k1.z) * (uz - k1.z);
    float d2 = (ux - k2.x) * (ux - k2.x) + (uy - k2.y) * (uy - k2.y) + (uz - k2.z) * (uz - k2.z);
    float r0 = 1.0f / (d0 + 1e-8f), r1 = 1.0f / (d1 + 1e-8f), r2 = 1.0f / (d2 + 1e-8f);
    float inv = 1.0f / (r0 + r1 + r2);
    size_t base = ((size_t)b * NPTS + i) * 3;
    g_idx3[base] = i0; g_idx3[base + 1] = i1; g_idx3[base + 2] = i2;
    g_w3[base] = r0 * inv; g_w3[base + 1] = r1 * inv; g_w3[base + 2] = r2 * inv;
}

// ---------------- known_feats transpose ----------------
__global__ void kft_kernel(const float* __restrict__ kf) {
    __shared__ float tile[32][33];
    int b = blockIdx.z, c0 = blockIdx.y * 32, j0 = blockIdx.x * 32;
    const float* src = kf + (size_t)b * CH * MPTS;
    for (int r = threadIdx.y; r < 32; r += 8)
        tile[r][threadIdx.x] = src[(size_t)(c0 + r) * MPTS + j0 + threadIdx.x];
    __syncthreads();
    __half* dst = g_kft + (size_t)b * MPTS * CH;
    for (int r = threadIdx.y; r < 32; r += 8)
        dst[(size_t)(j0 + r) * CH + c0 + threadIdx.x] = __float2half_rn(tile[threadIdx.x][r]);
}

// ---------------- GEMM geometry (2-stage, 2 blocks/SM) ----------------
#define HS      72
#define RS2H    136
#define ATILE_B (128 * HS * 2)
#define STAGE_B (2 * ATILE_B)
#define GEMM1_SMEM (2 * STAGE_B + 1024 + 4096)
#define GEMM2_SMEM (2 * STAGE_B + 2048)

// ---------------- GEMM1: A = [3NN-interp(kft) | uf-trans], B = W1h ; D(b,i,o) ----------------
__global__ void __launch_bounds__(256, 2) gemm1_f(__half* __restrict__ Dg,
                                                  float* __restrict__ sums,
                                                  float* __restrict__ sqs) {
    extern __shared__ char smc[];
    const uint32_t sbase = smem_u32(smc);
    float* ssum = (float*)(smc + 2 * STAGE_B);
    float* ssq  = ssum + 128;
    int*   sidx = (int*)(smc + 2 * STAGE_B + 1024);
    float* sw   = (float*)(smc + 2 * STAGE_B + 1024 + 2048);

    const int tid = threadIdx.x;
    const int wid = tid >> 5, l = tid & 31;
    const int wy = wid >> 2, wx = wid & 3;
    const int g = l >> 2, c4 = l & 3;
    const int lr = l & 7, sel = l >> 3;
    const int b = blockIdx.z;
    const int i0 = blockIdx.x * 128, o0 = blockIdx.y * 128;

    if (tid < 128) {
        ssum[tid] = 0.f; ssq[tid] = 0.f;
        size_t base = ((size_t)b * NPTS + i0 + tid) * 3;
        sidx[4 * tid] = g_idx3[base]; sidx[4 * tid + 1] = g_idx3[base + 1];
        sidx[4 * tid + 2] = g_idx3[base + 2];
        sw[4 * tid] = g_w3[base]; sw[4 * tid + 1] = g_w3[base + 1];
        sw[4 * tid + 2] = g_w3[base + 2];
    }
    __syncthreads();

    const __half* Xc = g_Xc + (size_t)b * CH * NPTS;
    const __half* Bbase = g_W1h + (size_t)o0 * K1;
    const __half* kftb = g_kft + (size_t)b * MPTS * CH;

    float acc[4][4][4];
    #pragma unroll
    for (int mi = 0; mi < 4; mi++)
        #pragma unroll
        for (int ni = 0; ni < 4; ni++)
            #pragma unroll
            for (int t = 0; t < 4; t++) acc[mi][ni][t] = 0.f;

    const int rb = tid >> 3, qq = tid & 7;
    const int NC = K1 / 64;

    uint4 areg[4];

    auto loadB = [&](int c, int s) {
        int k0 = c * 64;
        uint32_t offB = sbase + s * STAGE_B + ATILE_B;
        const __half* Bb = Bbase + k0;
        #pragma unroll
        for (int it = 0; it < 4; it++) {
            int r = rb + it * 32;
            cp16(offB + r * (HS * 2) + qq * 16, Bb + (size_t)r * K1 + qq * 8);
        }
        asm volatile("cp.async.commit_group;" ::: "memory");
    };
    auto ldgA = [&](int c) {
        int k0 = c * 64 + qq * 8;
        #pragma unroll
        for (int it = 0; it < 4; it++) {
            int r = rb + it * 32;
            int4 jj = *(const int4*)&sidx[4 * r];
            float4 ww = *(const float4*)&sw[4 * r];
            union { uint4 u; __half2 h[4]; } A0, A1, A2, R;
            A0.u = *(const uint4*)(kftb + (size_t)jj.x * CH + k0);
            A1.u = *(const uint4*)(kftb + (size_t)jj.y * CH + k0);
            A2.u = *(const uint4*)(kftb + (size_t)jj.z * CH + k0);
            #pragma unroll
            for (int j = 0; j < 4; j++) {
                float2 a = __half22float2(A0.h[j]);
                float2 d = __half22float2(A1.h[j]);
                float2 e = __half22float2(A2.h[j]);
                R.h[j] = __floats2half2_rn(ww.x * a.x + ww.y * d.x + ww.z * e.x,
                                           ww.x * a.y + ww.y * d.y + ww.z * e.y);
            }
            areg[it] = R.u;
        }
    };
    auto stsA = [&](int s) {
        #pragma unroll
        for (int it = 0; it < 4; it++)
            *(uint4*)(smc + s * STAGE_B + (rb + it * 32) * (HS * 2) + qq * 16) = areg[it];
    };
    auto loadAuf = [&](int c, int s) {
        int chb = (c - 4) * 64;
        uint32_t offA = sbase + s * STAGE_B;
        #pragma unroll
        for (int it = 0; it < 4; it++) {
            int idx = tid + it * 256;
            int row = idx >> 4;
            int off = idx & 15;
            cp16(offA + row * (RS2H * 2) + off * 16,
                 Xc + (size_t)(chb + row) * NPTS + i0 + off * 8);
        }
    };

    const uint32_t aLane = ((uint32_t)(wy * 64 + lr + ((sel & 1) << 3)) * HS + ((sel >> 1) << 3)) * 2;
    const uint32_t bLane = ((uint32_t)(wx * 32 + lr + ((sel >> 1) << 3)) * HS + ((sel & 1) << 3)) * 2;
    const uint32_t aLaneT = ((uint32_t)(lr + ((sel >> 1) << 3)) * RS2H + (wy * 64 + ((sel & 1) << 3))) * 2;

    ldgA(0); stsA(0); loadB(0, 0);
    ldgA(1); stsA(1); loadB(1, 1);

    for (int c = 0; c < NC; c++) {
        if (c + 1 < NC) {
            asm volatile("cp.async.wait_group 1;" ::: "memory");
        } else {
            asm volatile("cp.async.wait_group 0;" ::: "memory");
        }
        __syncthreads();

        if (c + 2 < 4) ldgA(c + 2);

        uint32_t sA = sbase + (c & 1) * STAGE_B;
        uint32_t sB = sA + ATILE_B;
        if (c < 4) {
            #pragma unroll
            for (int kk16 = 0; kk16 < 4; kk16++) {
                uint32_t koff = kk16 * 32;
                uint32_t af[4][4], bf[4][2];
                #pragma unroll
                for (int mi = 0; mi < 4; mi++)
                    ldm_x4(af[mi], sA + aLane + mi * (16 * HS * 2) + koff);
                #pragma unroll
                for (int nip = 0; nip < 2; nip++) {
                    uint32_t r[4];
                    ldm_x4(r, sB + bLane + nip * (16 * HS * 2) + koff);
                    bf[2 * nip][0] = r[0]; bf[2 * nip][1] = r[1];
                    bf[2 * nip + 1][0] = r[2]; bf[2 * nip + 1][1] = r[3];
                }
                #pragma unroll
                for (int mi = 0; mi < 4; mi++)
                    #pragma unroll
                    for (int ni = 0; ni < 4; ni++)
                        mma_f16(acc[mi][ni], af[mi], bf[ni]);
            }
        } else {
            #pragma unroll
            for (int kk16 = 0; kk16 < 4; kk16++) {
                uint32_t krowoff = kk16 * 16 * (RS2H * 2);
                uint32_t koff = kk16 * 32;
                uint32_t af[4][4], bf[4][2];
                #pragma unroll
                for (int mi = 0; mi < 4; mi++)
                    ldm_x4t(af[mi], sA + aLaneT + krowoff + mi * 32);
                #pragma unroll
                for (int nip = 0; nip < 2; nip++) {
                    uint32_t r[4];
                    ldm_x4(r, sB + bLane + nip * (16 * HS * 2) + koff);
                    bf[2 * nip][0] = r[0]; bf[2 * nip][1] = r[1];
                    bf[2 * nip + 1][0] = r[2]; bf[2 * nip + 1][1] = r[3];
                }
                #pragma unroll
                for (int mi = 0; mi < 4; mi++)
                    #pragma unroll
                    for (int ni = 0; ni < 4; ni++)
                        mma_f16(acc[mi][ni], af[mi], bf[ni]);
            }
        }
        __syncthreads();
        if (c + 2 < NC) {
            int s = (c + 2) & 1;
            if (c + 2 < 4) { stsA(s); } else { loadAuf(c + 2, s); }
            loadB(c + 2, s);
        }
    }

    // epilogue: D(b,i,o); stats per o-col
    #pragma unroll
    for (int mi = 0; mi < 4; mi++) {
        int row0 = i0 + wy * 64 + mi * 16 + g;
        #pragma unroll
        for (int ni = 0; ni < 4; ni++) {
            int col = o0 + wx * 32 + ni * 8 + 2 * c4;
            *(__half2*)(Dg + ((size_t)b * NPTS + row0) * CH + col) =
                __floats2half2_rn(acc[mi][ni][0], acc[mi][ni][1]);
            *(__half2*)(Dg + ((size_t)b * NPTS + row0 + 8) * CH + col) =
                __floats2half2_rn(acc[mi][ni][2], acc[mi][ni][3]);
        }
    }
    #pragma unroll
    for (int ni = 0; ni < 4; ni++) {
        float s0 = 0.f, s1 = 0.f, q0 = 0.f, q1 = 0.f;
        #pragma unroll
        for (int mi = 0; mi < 4; mi++) {
            const float* a = acc[mi][ni];
            s0 += a[0] + a[2]; s1 += a[1] + a[3];
            q0 += a[0] * a[0] + a[2] * a[2];
            q1 += a[1] * a[1] + a[3] * a[3];
        }
        int lc = wx * 32 + ni * 8 + 2 * c4;
        atomicAdd(&ssum[lc], s0); atomicAdd(&ssum[lc + 1], s1);
        atomicAdd(&ssq[lc], q0);  atomicAdd(&ssq[lc + 1], q1);
    }
    __syncthreads();
    if (tid < 128) {
        atomicAdd(&sums[o0 + tid], ssum[tid]);
        atomicAdd(&sqs[o0 + tid], ssq[tid]);
    }
}

// ---------------- GEMM2 (transposed output): A = W2h (o,k), B = relu(BN1(Hh)) (i,k); D(b,o,i) ----------------
__global__ void __launch_bounds__(256, 2) gemm2_f(const __half* __restrict__ Hg,
                                                  const __half* __restrict__ Wg,
                                                  __half* __restrict__ Dg,
                                                  const float* __restrict__ ga1,
                                                  const float* __restrict__ be1,
                                                  float* __restrict__ sums,
                                                  float* __restrict__ sqs) {
    extern __shared__ char smc[];
    const uint32_t sbase = smem_u32(smc);
    float* ssum = (float*)(smc + 2 * STAGE_B);
    float* ssq  = ssum + 128;
    __half* s_sc = (__half*)(smc + 2 * STAGE_B + 1024);
    __half* s_sh = s_sc + 256;

    const int tid = threadIdx.x;
    const int wid = tid >> 5, l = tid & 31;
    const int wy = wid >> 2, wx = wid & 3;
    const int g = l >> 2, c4 = l & 3;
    const int lr = l & 7, sel = l >> 3;
    const int b = blockIdx.z;
    const int i0 = blockIdx.x * 128, o0 = blockIdx.y * 128;

    {
        float inv = 1.0f / (float)(BB * NPTS);
        float mean = g_sum1[tid] * inv;
        float var = g_sq1[tid] * inv - mean * mean;
        float sc = ga1[tid] * rsqrtf(var + BN_EPS);
        float sh = be1[tid] - mean * sc;
        s_sc[tid] = __float2half_rn(sc);
        s_sh[tid] = __float2half_rn(sh);
    }
    if (tid < 128) { ssum[tid] = 0.f; ssq[tid] = 0.f; }
    __syncthreads();

    const __half* Hbase = Hg + ((size_t)b * NPTS + i0) * CH;   // B operand (i rows)
    const __half* Wbase = Wg + (size_t)o0 * CH;                 // A operand (o rows)

    float acc[4][4][4];
    #pragma unroll
    for (int mi = 0; mi < 4; mi++)
        #pragma unroll
        for (int ni = 0; ni < 4; ni++)
            #pragma unroll
            for (int t = 0; t < 4; t++) acc[mi][ni][t] = 0.f;

    const int rb = tid >> 3, qq = tid & 7;
    const int NC = CH / 64;

    uint4 areg[4], screg, shreg;

    auto loadA = [&](int c, int s) {   // W2h rows -> A tile, plain cp.async
        int k0 = c * 64;
        uint32_t offA = sbase + s * STAGE_B;
        const __half* Wb = Wbase + k0;
        #pragma unroll
        for (int it = 0; it < 4; it++) {
            int r = rb + it * 32;
            cp16(offA + r * (HS * 2) + qq * 16, Wb + (size_t)r * CH + qq * 8);
        }
        asm volatile("cp.async.commit_group;" ::: "memory");
    };
    auto ldgB = [&](int c) {           // H rows -> regs (BN applied at STS)
        int k0 = c * 64;
        #pragma unroll
        for (int it = 0; it < 4; it++)
            areg[it] = *(const uint4*)(Hbase + (size_t)(rb + it * 32) * CH + k0 + qq * 8);
        screg = *(const uint4*)(s_sc + k0 + qq * 8);
        shreg = *(const uint4*)(s_sh + k0 + qq * 8);
    };
    auto stsB = [&](int s) {
        const __half2 z2 = __float2half2_rn(0.f);
        union { uint4 u; __half2 h[4]; } sc, sh;
        sc.u = screg; sh.u = shreg;
        #pragma unroll
        for (int it = 0; it < 4; it++) {
            int r = rb + it * 32;
            union { uint4 u; __half2 h[4]; } v;
            v.u = areg[it];
            #pragma unroll
            for (int j = 0; j < 4; j++)
                v.h[j] = __hmax2(__hfma2(v.h[j], sc.h[j], sh.h[j]), z2);
            *(uint4*)(smc + s * STAGE_B + ATILE_B + r * (HS * 2) + qq * 16) = v.u;
        }
    };

    const uint32_t aLane = ((uint32_t)(wy * 64 + lr + ((sel & 1) << 3)) * HS + ((sel >> 1) << 3)) * 2;
    const uint32_t bLane = ((uint32_t)(wx * 32 + lr + ((sel >> 1) << 3)) * HS + ((sel & 1) << 3)) * 2;

    ldgB(0); stsB(0); loadA(0, 0);
    ldgB(1); stsB(1); loadA(1, 1);

    for (int c = 0; c < NC; c++) {
        if (c + 1 < NC) {
            asm volatile("cp.async.wait_group 1;" ::: "memory");
        } else {
            asm volatile("cp.async.wait_group 0;" ::: "memory");
        }
        __syncthreads();

        if (c + 2 < NC) ldgB(c + 2);

        uint32_t sA = sbase + (c & 1) * STAGE_B;
        uint32_t sB = sA + ATILE_B;
        #pragma unroll
        for (int kk16 = 0; kk16 < 4; kk16++) {
            uint32_t koff = kk16 * 32;
            uint32_t af[4][4], bf[4][2];
            #pragma unroll
            for (int mi = 0; mi < 4; mi++)
                ldm_x4(af[mi], sA + aLane + mi * (16 * HS * 2) + koff);
            #pragma unroll
            for (int nip = 0; nip < 2; nip++) {
                uint32_t r[4];
                ldm_x4(r, sB + bLane + nip * (16 * HS * 2) + koff);
                bf[2 * nip][0] = r[0]; bf[2 * nip][1] = r[1];
                bf[2 * nip + 1][0] = r[2]; bf[2 * nip + 1][1] = r[3];
            }
            #pragma unroll
            for (int mi = 0; mi < 4; mi++)
                #pragma unroll
                for (int ni = 0; ni < 4; ni++)
                    mma_f16(acc[mi][ni], af[mi], bf[ni]);
        }
        __syncthreads();
        if (c + 2 < NC) {
            int s = (c + 2) & 1;
            stsB(s);
            loadA(c + 2, s);
        }
    }

    // epilogue: D(b,o,i); rows = o, cols = i; stats per o-row
    #pragma unroll
    for (int mi = 0; mi < 4; mi++) {
        int row0 = o0 + wy * 64 + mi * 16 + g;
        float sl = 0.f, sh2 = 0.f, ql = 0.f, qh = 0.f;
        #pragma unroll
        for (int ni = 0; ni < 4; ni++) {
            int col = i0 + wx * 32 + ni * 8 + 2 * c4;
            const float* a = acc[mi][ni];
            *(__half2*)(Dg + ((size_t)b * CH + row0) * NPTS + col) =
                __floats2half2_rn(a[0], a[1]);
            *(__half2*)(Dg + ((size_t)b * CH + row0 + 8) * NPTS + col) =
                __floats2half2_rn(a[2], a[3]);
            sl += a[0] + a[1]; sh2 += a[2] + a[3];
            ql += a[0] * a[0] + a[1] * a[1];
            qh += a[2] * a[2] + a[3] * a[3];
        }
        int lc = wy * 64 + mi * 16 + g;
        atomicAdd(&ssum[lc], sl); atomicAdd(&ssum[lc + 8], sh2);
        atomicAdd(&ssq[lc], ql);  atomicAdd(&ssq[lc + 8], qh);
    }
    __syncthreads();
    if (tid < 128) {
        atomicAdd(&sums[o0 + tid], ssum[tid]);
        atomicAdd(&sqs[o0 + tid], ssq[tid]);
    }
}

// ---------------- final: elementwise BN2 + ReLU, (b,o,i) half -> f32 ----------------
__global__ void out_kernel(float* __restrict__ out,
                           const float* __restrict__ ga2, const float* __restrict__ be2) {
    size_t q = (size_t)blockIdx.x * 256 + threadIdx.x;   // one 4-half chunk
    int o = (int)((q >> 10) & (CH - 1));                 // 1024 chunks per o-row
    float inv = 1.0f / (float)(BB * NPTS);
    float mean = g_sum2[o] * inv;
    float var = g_sq2[o] * inv - mean * mean;
    float sc = ga2[o] * rsqrtf(var + BN_EPS);
    float sh = be2[o] - mean * sc;
    union { uint2 u; __half2 h[2]; } v;
    v.u = *(const uint2*)(g_Y2t + q * 4);
    float2 f0 = __half22float2(v.h[0]);
    float2 f1 = __half22float2(v.h[1]);
    float4 r;
    r.x = fmaxf(fmaf(f0.x, sc, sh), 0.f);
    r.y = fmaxf(fmaf(f0.y, sc, sh), 0.f);
    r.z = fmaxf(fmaf(f1.x, sc, sh), 0.f);
    r.w = fmaxf(fmaf(f1.y, sc, sh), 0.f);
    ((float4*)out)[q] = r;
}

// ---------------- launch ----------------
extern "C" void kernel_launch(void* const* d_in, const int* in_sizes, int n_in,
                              void* d_out, int out_size) {
    const float* unknown = (const float*)d_in[0];
    const float* known   = (const float*)d_in[1];
    const float* uf      = (const float*)d_in[2];
    const float* kf      = (const float*)d_in[3];
    const float* W1      = (const float*)d_in[4];
    const float* g1      = (const float*)d_in[5];
    const float* be1     = (const float*)d_in[6];
    const float* W2      = (const float*)d_in[7];
    const float* g2      = (const float*)d_in[8];
    const float* be2     = (const float*)d_in[9];
    float* out = (float*)d_out;

    static cudaStream_t s1 = nullptr, s2 = nullptr;
    static cudaEvent_t ev0 = nullptr, ev1 = nullptr, ev2 = nullptr;
    if (!s1) {
        cudaStreamCreateWithFlags(&s1, cudaStreamNonBlocking);
        cudaStreamCreateWithFlags(&s2, cudaStreamNonBlocking);
        cudaEventCreateWithFlags(&ev0, cudaEventDisableTiming);
        cudaEventCreateWithFlags(&ev1, cudaEventDisableTiming);
        cudaEventCreateWithFlags(&ev2, cudaEventDisableTiming);
        cudaFuncSetAttribute(gemm1_f, cudaFuncAttributeMaxDynamicSharedMemorySize, GEMM1_SMEM);
        cudaFuncSetAttribute(gemm2_f, cudaFuncAttributeMaxDynamicSharedMemorySize, GEMM2_SMEM);
    }

    __half *pHh, *pY2t, *pW2h;
    float *ps1, *pq1, *ps2, *pq2;
    cudaGetSymbolAddress((void**)&pHh, g_Hh);
    cudaGetSymbolAddress((void**)&pY2t, g_Y2t);
    cudaGetSymbolAddress((void**)&pW2h, g_W2h);
    cudaGetSymbolAddress((void**)&ps1, g_sum1);
    cudaGetSymbolAddress((void**)&pq1, g_sq1);
    cudaGetSymbolAddress((void**)&ps2, g_sum2);
    cudaGetSymbolAddress((void**)&pq2, g_sq2);

    cudaEventRecord(ev0, 0);
    cudaStreamWaitEvent(s1, ev0, 0);
    cudaStreamWaitEvent(s2, ev0, 0);

    nn_kernel<<<dim3(NPTS / 256, BB), 256>>>(unknown, known);                      // main
    kft_kernel<<<dim3(MPTS / 32, CH / 32, BB), dim3(32, 8), 0, s1>>>(kf);          // s1
    prep_kernel<<<CH * K1 / 256 + CH * CH / 256 + 1, 256, 0, s1>>>(W1, W2);        // s1
    cvt_kernel<<<(int)(((size_t)BB * CH * NPTS / 4) / 256), 256, 0, s2>>>(uf);     // s2

    cudaEventRecord(ev1, s1);
    cudaEventRecord(ev2, s2);
    cudaStreamWaitEvent(0, ev1, 0);
    cudaStreamWaitEvent(0, ev2, 0);

    gemm1_f<<<dim3(NPTS / 128, CH / 128, BB), 256, GEMM1_SMEM>>>(pHh, ps1, pq1);
    gemm2_f<<<dim3(NPTS / 128, CH / 128, BB), 256, GEMM2_SMEM>>>(pHh, pW2h, pY2t, g1, be1, ps2, pq2);
    out_kernel<<<(int)(((size_t)BB * CH * NPTS / 4) / 256), 256>>>(out, g2, be2);
}